// round 2
// baseline (speedup 1.0000x reference)
#include <cuda_runtime.h>

#define D 128
#define NMAX 50000
#define EMAX 500000
#define TTYPES 4
#define BM 128
#define BK 16

// Scratch (device globals: allocation-free rule)
__device__ float g_A[(size_t)TTYPES * NMAX * D];   // per-type scatter of x[col]
__device__ float g_S[(size_t)NMAX * D];            // scatter of relu(ef@W1+b1)
__device__ int   g_cnt[TTYPES * NMAX];             // per (type,node) edge counts

// ---------------------------------------------------------------------------
__global__ void k_zero(int N) {
    size_t nA4 = (size_t)TTYPES * N * D / 4;
    size_t nS4 = (size_t)N * D / 4;
    size_t nC  = (size_t)TTYPES * N;
    size_t stride = (size_t)gridDim.x * blockDim.x;
    size_t i0 = (size_t)blockIdx.x * blockDim.x + threadIdx.x;
    float4 z = make_float4(0.f, 0.f, 0.f, 0.f);
    float4* A4 = (float4*)g_A;
    float4* S4 = (float4*)g_S;
    for (size_t i = i0; i < nA4; i += stride) A4[i] = z;
    for (size_t i = i0; i < nS4; i += stride) S4[i] = z;
    for (size_t i = i0; i < nC;  i += stride) g_cnt[i] = 0;
}

// ---------------------------------------------------------------------------
// One warp per edge: g_A[type][row] += x[col]; g_cnt[type][row] += 1
__global__ void k_scatter(const float* __restrict__ x, const int* __restrict__ ei,
                          const int* __restrict__ et, int N, int E) {
    int w = (int)((blockIdx.x * (size_t)blockDim.x + threadIdx.x) >> 5);
    int lane = threadIdx.x & 31;
    if (w >= E) return;
    int row = __ldg(ei + w);        // destination
    int col = __ldg(ei + E + w);    // source (gathered)
    int t   = __ldg(et + w);
    float4 v = *(const float4*)(x + (size_t)col * D + lane * 4);
    float* dst = g_A + ((size_t)t * N + row) * D + lane * 4;
    atomicAdd(dst + 0, v.x);
    atomicAdd(dst + 1, v.y);
    atomicAdd(dst + 2, v.z);
    atomicAdd(dst + 3, v.w);
    if (lane == 0) atomicAdd(&g_cnt[t * N + row], 1);
}

// ---------------------------------------------------------------------------
// H = relu(ef @ W1 + b1), scatter-add H into g_S[row]. Tiled fp32 GEMM.
// 256 threads, BM=128 edges x 128 cols, 8x8 micro-tiles.
__global__ void k_edge_mlp(const float* __restrict__ ef, const int* __restrict__ ei,
                           const float* __restrict__ W1, const float* __restrict__ b1,
                           int N, int E) {
    __shared__ __align__(16) float As[BK][BM + 4];   // transposed ef tile
    __shared__ __align__(16) float Bs[BK][D];        // W1 tile
    int tid = threadIdx.x;
    int tx = tid & 15, ty = tid >> 4;
    int e0 = blockIdx.x * BM;
    float acc[8][8] = {};

    for (int k0 = 0; k0 < D; k0 += BK) {
        // A tile: ef[e0+r][k0+c], 512 float4s
        for (int f = tid; f < (BM * BK / 4); f += 256) {
            int r  = f >> 2;
            int c4 = (f & 3) * 4;
            float4 v = make_float4(0.f, 0.f, 0.f, 0.f);
            int e = e0 + r;
            if (e < E) v = *(const float4*)(ef + (size_t)e * D + k0 + c4);
            As[c4 + 0][r] = v.x; As[c4 + 1][r] = v.y;
            As[c4 + 2][r] = v.z; As[c4 + 3][r] = v.w;
        }
        // B tile: W1[k0+k][j]
        for (int f = tid; f < (BK * D / 4); f += 256) {
            int k  = f >> 5;
            int j4 = (f & 31) * 4;
            *(float4*)&Bs[k][j4] = *(const float4*)(W1 + (size_t)(k0 + k) * D + j4);
        }
        __syncthreads();
        #pragma unroll
        for (int kk = 0; kk < BK; kk++) {
            float a[8], b[8];
            *(float4*)&a[0] = *(const float4*)&As[kk][ty * 8];
            *(float4*)&a[4] = *(const float4*)&As[kk][ty * 8 + 4];
            *(float4*)&b[0] = *(const float4*)&Bs[kk][tx * 8];
            *(float4*)&b[4] = *(const float4*)&Bs[kk][tx * 8 + 4];
            #pragma unroll
            for (int i = 0; i < 8; i++)
                #pragma unroll
                for (int j = 0; j < 8; j++)
                    acc[i][j] += a[i] * b[j];
        }
        __syncthreads();
    }

    float bb[8];
    *(float4*)&bb[0] = *(const float4*)(b1 + tx * 8);
    *(float4*)&bb[4] = *(const float4*)(b1 + tx * 8 + 4);
    #pragma unroll
    for (int i = 0; i < 8; i++) {
        int e = e0 + ty * 8 + i;
        if (e < E) {
            int r = __ldg(ei + e);   // destination row
            float* dst = g_S + (size_t)r * D + tx * 8;
            #pragma unroll
            for (int j = 0; j < 8; j++) {
                float v = acc[i][j] + bb[j];
                v = v > 0.f ? v : 0.f;
                atomicAdd(dst + j, v);
            }
        }
    }
}

// ---------------------------------------------------------------------------
// out[n] = sum_t A_t[n]@W_t + S[n]@W_e2 + x[n]@W_self
//          + sum_t cnt_t[n]*b_t + cnt_tot[n]*b_e2 + b_self ; then LN + ReLU
// Single GEMM over 6 K-segments of 128.
__global__ void k_final(const float* __restrict__ x,
                        const float* __restrict__ W_types, const float* __restrict__ b_types,
                        const float* __restrict__ W_self,  const float* __restrict__ b_self,
                        const float* __restrict__ W_e2,    const float* __restrict__ b_e2,
                        const float* __restrict__ ln_g,    const float* __restrict__ ln_b,
                        float* __restrict__ out, int N) {
    __shared__ __align__(16) float As[BK][BM + 4];
    __shared__ __align__(16) float Bs[BK][D];
    __shared__ float Ps[1024];   // biases+LN: [0,512)=b_types, 512 b_e2, 640 b_self, 768 ln_g, 896 ln_b
    int tid = threadIdx.x;
    int tx = tid & 15, ty = tid >> 4;
    int n0 = blockIdx.x * BM;
    float acc[8][8] = {};

    for (int f = tid; f < 1024; f += 256) {
        float v;
        if (f < 512)      v = b_types[f];
        else if (f < 640) v = b_e2[f - 512];
        else if (f < 768) v = b_self[f - 640];
        else if (f < 896) v = ln_g[f - 768];
        else              v = ln_b[f - 896];
        Ps[f] = v;
    }

    for (int seg = 0; seg < 6; seg++) {
        const float* Ab = (seg < 4) ? (g_A + (size_t)seg * N * D)
                                    : (seg == 4 ? g_S : x);
        const float* Bb = (seg < 4) ? (W_types + (size_t)seg * D * D)
                                    : (seg == 4 ? W_e2 : W_self);
        for (int k0 = 0; k0 < D; k0 += BK) {
            for (int f = tid; f < (BM * BK / 4); f += 256) {
                int r  = f >> 2;
                int c4 = (f & 3) * 4;
                float4 v = make_float4(0.f, 0.f, 0.f, 0.f);
                int n = n0 + r;
                if (n < N) v = *(const float4*)(Ab + (size_t)n * D + k0 + c4);
                As[c4 + 0][r] = v.x; As[c4 + 1][r] = v.y;
                As[c4 + 2][r] = v.z; As[c4 + 3][r] = v.w;
            }
            for (int f = tid; f < (BK * D / 4); f += 256) {
                int k  = f >> 5;
                int j4 = (f & 31) * 4;
                *(float4*)&Bs[k][j4] = *(const float4*)(Bb + (size_t)(k0 + k) * D + j4);
            }
            __syncthreads();
            #pragma unroll
            for (int kk = 0; kk < BK; kk++) {
                float a[8], b[8];
                *(float4*)&a[0] = *(const float4*)&As[kk][ty * 8];
                *(float4*)&a[4] = *(const float4*)&As[kk][ty * 8 + 4];
                *(float4*)&b[0] = *(const float4*)&Bs[kk][tx * 8];
                *(float4*)&b[4] = *(const float4*)&Bs[kk][tx * 8 + 4];
                #pragma unroll
                for (int i = 0; i < 8; i++)
                    #pragma unroll
                    for (int j = 0; j < 8; j++)
                        acc[i][j] += a[i] * b[j];
            }
            __syncthreads();
        }
    }

    // Epilogue: biases + LayerNorm + ReLU
    #pragma unroll
    for (int i = 0; i < 8; i++) {
        int n = n0 + ty * 8 + i;
        bool valid = n < N;
        float c0 = 0.f, c1 = 0.f, c2 = 0.f, c3 = 0.f;
        if (valid) {
            c0 = (float)g_cnt[0 * N + n];
            c1 = (float)g_cnt[1 * N + n];
            c2 = (float)g_cnt[2 * N + n];
            c3 = (float)g_cnt[3 * N + n];
        }
        float ct = c0 + c1 + c2 + c3;
        float v[8];
        float s1 = 0.f, s2 = 0.f;
        #pragma unroll
        for (int j = 0; j < 8; j++) {
            int jj = tx * 8 + j;
            float val = acc[i][j]
                + c0 * Ps[0 * D + jj] + c1 * Ps[1 * D + jj]
                + c2 * Ps[2 * D + jj] + c3 * Ps[3 * D + jj]
                + ct * Ps[512 + jj] + Ps[640 + jj];
            v[j] = val;
            s1 += val;
            s2 += val * val;
        }
        // reduce across the 16-lane tx group (same row)
        #pragma unroll
        for (int m = 1; m < 16; m <<= 1) {
            s1 += __shfl_xor_sync(0xffffffff, s1, m);
            s2 += __shfl_xor_sync(0xffffffff, s2, m);
        }
        float mean = s1 * (1.f / D);
        float var  = s2 * (1.f / D) - mean * mean;
        float inv  = rsqrtf(var + 1e-5f);
        if (valid) {
            #pragma unroll
            for (int j = 0; j < 8; j++) {
                int jj = tx * 8 + j;
                float r = (v[j] - mean) * inv * Ps[768 + jj] + Ps[896 + jj];
                out[(size_t)n * D + jj] = r > 0.f ? r : 0.f;
            }
        }
    }
}

// ---------------------------------------------------------------------------
extern "C" void kernel_launch(void* const* d_in, const int* in_sizes, int n_in,
                              void* d_out, int out_size) {
    const float* x   = (const float*)d_in[0];
    const int*   ei  = (const int*)d_in[1];
    const int*   et  = (const int*)d_in[2];
    const float* ef  = (const float*)d_in[3];
    const float* Wt  = (const float*)d_in[4];
    const float* bt  = (const float*)d_in[5];
    const float* Ws  = (const float*)d_in[6];
    const float* bs  = (const float*)d_in[7];
    const float* W1  = (const float*)d_in[8];
    const float* b1  = (const float*)d_in[9];
    const float* W2  = (const float*)d_in[10];
    const float* b2  = (const float*)d_in[11];
    const float* lg  = (const float*)d_in[12];
    const float* lb  = (const float*)d_in[13];
    float* out = (float*)d_out;

    int N = in_sizes[0] / D;
    int E = in_sizes[2];

    k_zero<<<2048, 256>>>(N);
    k_scatter<<<(E + 7) / 8, 256>>>(x, ei, et, N, E);
    k_edge_mlp<<<(E + BM - 1) / BM, 256>>>(ef, ei, W1, b1, N, E);
    k_final<<<(N + BM - 1) / BM, 256>>>(x, Wt, bt, Ws, bs, W2, b2, lg, lb, out, N);
}

// round 4
// speedup vs baseline: 1.5180x; 1.5180x over previous
#include <cuda_runtime.h>
#include <cuda_bf16.h>
#include <cstdint>

#define D 128
#define NMAX 50000
#define TTYPES 4

#define ASTRIDE 136   // bf16 elems per row (pad for conflict-free ldmatrix)
#define BSTRIDE 136
#define A_BYTES (128 * ASTRIDE * 2)     // 34816
#define SMEM_BYTES (4 * A_BYTES)        // Ah, Al, Bh, Bl = 139264

// Scratch (device globals: allocation-free rule)
__device__ float g_A[(size_t)TTYPES * NMAX * D];   // per-type scatter of x[col]
__device__ float g_S[(size_t)NMAX * D];            // scatter of relu(ef@W1+b1)
__device__ int   g_cnt[TTYPES * NMAX];             // per (type,node) edge counts

// ---------------------------------------------------------------------------
__device__ __forceinline__ uint32_t smem_u32(const void* p) {
    return (uint32_t)__cvta_generic_to_shared(p);
}

__device__ __forceinline__ void split_bf(float a, __nv_bfloat16& h, __nv_bfloat16& l) {
    h = __float2bfloat16_rn(a);
    l = __float2bfloat16_rn(a - __bfloat162float(h));
}

__device__ __forceinline__ void store4_split(__nv_bfloat16* Hrow, __nv_bfloat16* Lrow,
                                             int c, float4 v) {
    __nv_bfloat16 h0, l0, h1, l1, h2, l2, h3, l3;
    split_bf(v.x, h0, l0); split_bf(v.y, h1, l1);
    split_bf(v.z, h2, l2); split_bf(v.w, h3, l3);
    *(__nv_bfloat162*)(Hrow + c)     = __halves2bfloat162(h0, h1);
    *(__nv_bfloat162*)(Hrow + c + 2) = __halves2bfloat162(h2, h3);
    *(__nv_bfloat162*)(Lrow + c)     = __halves2bfloat162(l0, l1);
    *(__nv_bfloat162*)(Lrow + c + 2) = __halves2bfloat162(l2, l3);
}

#define LDMX4(r0, r1, r2, r3, addr) \
    asm volatile("ldmatrix.sync.aligned.m8n8.x4.shared.b16 {%0,%1,%2,%3},[%4];" \
                 : "=r"(r0), "=r"(r1), "=r"(r2), "=r"(r3) : "r"(addr))

#define LDMX2T(r0, r1, addr) \
    asm volatile("ldmatrix.sync.aligned.m8n8.x2.trans.shared.b16 {%0,%1},[%2];" \
                 : "=r"(r0), "=r"(r1) : "r"(addr))

#define MMA_BF16(d, a0, a1, a2, a3, b0, b1) \
    asm volatile("mma.sync.aligned.m16n8k16.row.col.f32.bf16.bf16.f32 " \
                 "{%0,%1,%2,%3},{%4,%5,%6,%7},{%8,%9},{%0,%1,%2,%3};" \
                 : "+f"(d[0]), "+f"(d[1]), "+f"(d[2]), "+f"(d[3]) \
                 : "r"(a0), "r"(a1), "r"(a2), "r"(a3), "r"(b0), "r"(b1))

#define REDV4(ptr, v0, v1, v2, v3) \
    asm volatile("red.global.add.v4.f32 [%0], {%1,%2,%3,%4};" \
                 :: "l"(ptr), "f"(v0), "f"(v1), "f"(v2), "f"(v3) : "memory")

// C[128x128] += A[128x128] * B[128x128] with split-2 bf16 (3 MMA).
// Warp w computes rows [w*16, w*16+16), all 128 cols. acc[nt][0..3].
__device__ __forceinline__ void mma_K128(char* smem, int wid, int lane,
                                         float acc[16][4]) {
    __nv_bfloat16* Ah = (__nv_bfloat16*)smem;
    uint32_t aH = smem_u32(Ah + (wid * 16 + (lane & 15)) * ASTRIDE + ((lane >> 4) * 8));
    uint32_t aL = aH + A_BYTES;
    uint32_t bH = smem_u32((__nv_bfloat16*)(smem + 2 * A_BYTES) + (lane & 15) * BSTRIDE);
    uint32_t bL = bH + A_BYTES;

    for (int ks = 0; ks < 8; ks++) {
        uint32_t ao = aH + ks * 32;               // advance 16 bf16 along k
        uint32_t ah0, ah1, ah2, ah3, al0, al1, al2, al3;
        LDMX4(ah0, ah1, ah2, ah3, ao);
        LDMX4(al0, al1, al2, al3, ao + A_BYTES);
        uint32_t br = bH + ks * (16 * BSTRIDE * 2);   // advance 16 k-rows
        #pragma unroll
        for (int nt = 0; nt < 16; nt++) {
            uint32_t ba = br + nt * 16;
            uint32_t bh0, bh1, bl0, bl1;
            LDMX2T(bh0, bh1, ba);
            LDMX2T(bl0, bl1, ba + (bL - bH));
            MMA_BF16(acc[nt], al0, al1, al2, al3, bh0, bh1);
            MMA_BF16(acc[nt], ah0, ah1, ah2, ah3, bl0, bl1);
            MMA_BF16(acc[nt], ah0, ah1, ah2, ah3, bh0, bh1);
        }
    }
}

// ---------------------------------------------------------------------------
__global__ void k_zero(int N) {
    size_t nA4 = (size_t)TTYPES * N * D / 4;
    size_t nS4 = (size_t)N * D / 4;
    size_t nC  = (size_t)TTYPES * N;
    size_t stride = (size_t)gridDim.x * blockDim.x;
    size_t i0 = (size_t)blockIdx.x * blockDim.x + threadIdx.x;
    float4 z = make_float4(0.f, 0.f, 0.f, 0.f);
    float4* A4 = (float4*)g_A;
    float4* S4 = (float4*)g_S;
    for (size_t i = i0; i < nA4; i += stride) A4[i] = z;
    for (size_t i = i0; i < nS4; i += stride) S4[i] = z;
    for (size_t i = i0; i < nC;  i += stride) g_cnt[i] = 0;
}

// ---------------------------------------------------------------------------
// One warp per edge: g_A[type][row] += x[col] (float4 red); counts.
__global__ void k_scatter(const float* __restrict__ x, const int* __restrict__ ei,
                          const int* __restrict__ et, int N, int E) {
    int w = (int)(((size_t)blockIdx.x * blockDim.x + threadIdx.x) >> 5);
    int lane = threadIdx.x & 31;
    if (w >= E) return;
    int row = __ldg(ei + w);        // destination
    int col = __ldg(ei + E + w);    // source (gathered)
    int t   = __ldg(et + w);
    float4 v = *(const float4*)(x + (size_t)col * D + lane * 4);
    float* p = g_A + ((size_t)t * N + row) * D + lane * 4;
    REDV4(p, v.x, v.y, v.z, v.w);
    if (lane == 0) atomicAdd(&g_cnt[t * N + row], 1);
}

// ---------------------------------------------------------------------------
// H = relu(ef @ W1 + b1) via bf16-split MMA, scatter-add H into g_S[row].
__global__ void __launch_bounds__(256, 1)
k_edge_mlp(const float* __restrict__ ef, const int* __restrict__ ei,
           const float* __restrict__ W1, const float* __restrict__ b1,
           int N, int E) {
    extern __shared__ char smem[];
    __nv_bfloat16* Ah = (__nv_bfloat16*)smem;
    __nv_bfloat16* Al = (__nv_bfloat16*)(smem + A_BYTES);
    __nv_bfloat16* Bh = (__nv_bfloat16*)(smem + 2 * A_BYTES);
    __nv_bfloat16* Bl = (__nv_bfloat16*)(smem + 3 * A_BYTES);
    int tid = threadIdx.x, wid = tid >> 5, lane = tid & 31;
    size_t e0 = (size_t)blockIdx.x * 128;

    // Fill A = ef tile [128 edges][128 k]
    for (int idx = tid; idx < 128 * 32; idx += 256) {
        int r = idx >> 5, c4 = (idx & 31) * 4;
        float4 v = make_float4(0.f, 0.f, 0.f, 0.f);
        size_t e = e0 + r;
        if (e < (size_t)E) v = *(const float4*)(ef + e * D + c4);
        store4_split(Ah + r * ASTRIDE, Al + r * ASTRIDE, c4, v);
    }
    // Fill B = W1 [k][n]
    for (int idx = tid; idx < 128 * 32; idx += 256) {
        int k = idx >> 5, n4 = (idx & 31) * 4;
        float4 v = *(const float4*)(W1 + (size_t)k * D + n4);
        store4_split(Bh + k * BSTRIDE, Bl + k * BSTRIDE, n4, v);
    }
    __syncthreads();

    float acc[16][4] = {};
    mma_K128(smem, wid, lane, acc);

    // Round-trip through smem so the scatter is float4-contiguous per edge.
    __syncthreads();
    float* S = (float*)smem;   // [128][132]
    int r0 = wid * 16 + (lane >> 2);
    int cp = (lane & 3) * 2;
    #pragma unroll
    for (int nt = 0; nt < 16; nt++) {
        int c = nt * 8 + cp;
        S[r0 * 132 + c]           = acc[nt][0];
        S[r0 * 132 + c + 1]       = acc[nt][1];
        S[(r0 + 8) * 132 + c]     = acc[nt][2];
        S[(r0 + 8) * 132 + c + 1] = acc[nt][3];
    }
    __syncthreads();

    float4 bb = __ldg((const float4*)b1 + lane);
    for (int it = 0; it < 16; it++) {
        int el = it * 8 + wid;
        size_t e = e0 + el;
        if (e < (size_t)E) {
            int dst = __ldg(ei + e);
            const float* Sr = S + el * 132 + lane * 4;
            float v0 = fmaxf(Sr[0] + bb.x, 0.f);
            float v1 = fmaxf(Sr[1] + bb.y, 0.f);
            float v2 = fmaxf(Sr[2] + bb.z, 0.f);
            float v3 = fmaxf(Sr[3] + bb.w, 0.f);
            float* p = g_S + (size_t)dst * D + lane * 4;
            REDV4(p, v0, v1, v2, v3);
        }
    }
}

// ---------------------------------------------------------------------------
// out[n] = sum over 6 K-segments (A_t@W_t, S@W_e2, x@W_self) + count-weighted
// biases, then LayerNorm + ReLU. bf16-split MMA per segment.
__global__ void __launch_bounds__(256, 1)
k_final(const float* __restrict__ x,
        const float* __restrict__ W_types, const float* __restrict__ b_types,
        const float* __restrict__ W_self,  const float* __restrict__ b_self,
        const float* __restrict__ W_e2,    const float* __restrict__ b_e2,
        const float* __restrict__ ln_g,    const float* __restrict__ ln_b,
        float* __restrict__ out, int N) {
    extern __shared__ char smem[];
    __shared__ float Ps[1024];  // [0,512) b_types, 512 b_e2, 640 b_self, 768 ln_g, 896 ln_b
    __nv_bfloat16* Ah = (__nv_bfloat16*)smem;
    __nv_bfloat16* Al = (__nv_bfloat16*)(smem + A_BYTES);
    __nv_bfloat16* Bh = (__nv_bfloat16*)(smem + 2 * A_BYTES);
    __nv_bfloat16* Bl = (__nv_bfloat16*)(smem + 3 * A_BYTES);
    int tid = threadIdx.x, wid = tid >> 5, lane = tid & 31;
    int n0 = blockIdx.x * 128;

    for (int f = tid; f < 1024; f += 256) {
        float v;
        if (f < 512)      v = b_types[f];
        else if (f < 640) v = b_e2[f - 512];
        else if (f < 768) v = b_self[f - 640];
        else if (f < 896) v = ln_g[f - 768];
        else              v = ln_b[f - 896];
        Ps[f] = v;
    }

    float acc[16][4] = {};
    for (int seg = 0; seg < 6; seg++) {
        const float* Ab = (seg < 4) ? (g_A + (size_t)seg * N * D)
                                    : (seg == 4 ? g_S : x);
        const float* Bb = (seg < 4) ? (W_types + (size_t)seg * D * D)
                                    : (seg == 4 ? W_e2 : W_self);
        __syncthreads();
        for (int idx = tid; idx < 128 * 32; idx += 256) {
            int r = idx >> 5, c4 = (idx & 31) * 4;
            float4 v = make_float4(0.f, 0.f, 0.f, 0.f);
            int n = n0 + r;
            if (n < N) v = *(const float4*)(Ab + (size_t)n * D + c4);
            store4_split(Ah + r * ASTRIDE, Al + r * ASTRIDE, c4, v);
        }
        for (int idx = tid; idx < 128 * 32; idx += 256) {
            int k = idx >> 5, n4 = (idx & 31) * 4;
            float4 v = *(const float4*)(Bb + (size_t)k * D + n4);
            store4_split(Bh + k * BSTRIDE, Bl + k * BSTRIDE, n4, v);
        }
        __syncthreads();
        mma_K128(smem, wid, lane, acc);
    }

    // Epilogue: count-weighted biases + LayerNorm + ReLU
    int p = lane & 3;
    #pragma unroll
    for (int half = 0; half < 2; half++) {
        int n = n0 + wid * 16 + (lane >> 2) + half * 8;
        bool valid = n < N;
        float c0 = 0.f, c1 = 0.f, c2 = 0.f, c3 = 0.f;
        if (valid) {
            c0 = (float)g_cnt[0 * N + n];
            c1 = (float)g_cnt[1 * N + n];
            c2 = (float)g_cnt[2 * N + n];
            c3 = (float)g_cnt[3 * N + n];
        }
        float ct = c0 + c1 + c2 + c3;
        float s1 = 0.f, s2 = 0.f;
        #pragma unroll
        for (int nt = 0; nt < 16; nt++) {
            #pragma unroll
            for (int j = 0; j < 2; j++) {
                int col = nt * 8 + p * 2 + j;
                float v = acc[nt][half * 2 + j]
                    + c0 * Ps[0 * D + col] + c1 * Ps[1 * D + col]
                    + c2 * Ps[2 * D + col] + c3 * Ps[3 * D + col]
                    + ct * Ps[512 + col] + Ps[640 + col];
                s1 += v;
                s2 += v * v;
            }
        }
        // reduce over the 4 lanes (lane bits 0-1) holding the same row
        s1 += __shfl_xor_sync(0xffffffff, s1, 1);
        s2 += __shfl_xor_sync(0xffffffff, s2, 1);
        s1 += __shfl_xor_sync(0xffffffff, s1, 2);
        s2 += __shfl_xor_sync(0xffffffff, s2, 2);
        float mean = s1 * (1.f / D);
        float var  = s2 * (1.f / D) - mean * mean;
        float inv  = rsqrtf(var + 1e-5f);
        if (valid) {
            #pragma unroll
            for (int nt = 0; nt < 16; nt++) {
                int col = nt * 8 + p * 2;
                float2 o;
                #pragma unroll
                for (int j = 0; j < 2; j++) {
                    float v = acc[nt][half * 2 + j]
                        + c0 * Ps[0 * D + col + j] + c1 * Ps[1 * D + col + j]
                        + c2 * Ps[2 * D + col + j] + c3 * Ps[3 * D + col + j]
                        + ct * Ps[512 + col + j] + Ps[640 + col + j];
                    float r = (v - mean) * inv * Ps[768 + col + j] + Ps[896 + col + j];
                    (&o.x)[j] = r > 0.f ? r : 0.f;
                }
                *(float2*)(out + (size_t)n * D + col) = o;
            }
        }
    }
}

// ---------------------------------------------------------------------------
extern "C" void kernel_launch(void* const* d_in, const int* in_sizes, int n_in,
                              void* d_out, int out_size) {
    const float* x   = (const float*)d_in[0];
    const int*   ei  = (const int*)d_in[1];
    const int*   et  = (const int*)d_in[2];
    const float* ef  = (const float*)d_in[3];
    const float* Wt  = (const float*)d_in[4];
    const float* bt  = (const float*)d_in[5];
    const float* Ws  = (const float*)d_in[6];
    const float* bs  = (const float*)d_in[7];
    const float* W1  = (const float*)d_in[8];
    const float* b1  = (const float*)d_in[9];
    const float* W2  = (const float*)d_in[10];
    const float* b2  = (const float*)d_in[11];
    const float* lg  = (const float*)d_in[12];
    const float* lb  = (const float*)d_in[13];
    float* out = (float*)d_out;

    int N = in_sizes[0] / D;
    int E = in_sizes[2];

    cudaFuncSetAttribute(k_edge_mlp, cudaFuncAttributeMaxDynamicSharedMemorySize, SMEM_BYTES);
    cudaFuncSetAttribute(k_final,    cudaFuncAttributeMaxDynamicSharedMemorySize, SMEM_BYTES);

    k_zero<<<2048, 256>>>(N);
    k_scatter<<<(E + 7) / 8, 256>>>(x, ei, et, N, E);
    k_edge_mlp<<<(E + 127) / 128, 256, SMEM_BYTES>>>(ef, ei, W1, b1, N, E);
    k_final<<<(N + 127) / 128, 256, SMEM_BYTES>>>(x, Wt, bt, Ws, bs, W2, b2, lg, lb, out, N);
}

// round 6
// speedup vs baseline: 2.2864x; 1.5062x over previous
#include <cuda_runtime.h>
#include <cuda_bf16.h>
#include <cstdint>

#define D 128
#define NMAX 50000
#define TTYPES 4

#define ASTRIDE 136               // bf16 elems per row (pad for conflict-free ldmatrix)
#define A_BYTES (64 * ASTRIDE * 2)       // 17408 (64-row tile, one split half)
#define B_BYTES (128 * ASTRIDE * 2)      // 34816 (128-k weight tile, one half)
#define SMEM_BYTES (2 * A_BYTES + 2 * B_BYTES)   // 104448

// Scratch (device globals: allocation-free rule)
__device__ float g_A[(size_t)TTYPES * NMAX * D];   // per-type scatter of x[col]
__device__ float g_S[(size_t)NMAX * D];            // scatter of relu(ef@W1+b1)
__device__ int   g_cnt[TTYPES * NMAX];             // per (type,node) edge counts
// pre-split weights: [0..3]=W_types, [4]=W_e2, [5]=W_self, [6]=W1
__device__ __nv_bfloat16 g_Wh[7 * D * D];
__device__ __nv_bfloat16 g_Wl[7 * D * D];

// ---------------------------------------------------------------------------
__device__ __forceinline__ uint32_t smem_u32(const void* p) {
    return (uint32_t)__cvta_generic_to_shared(p);
}

__device__ __forceinline__ void split_bf(float a, __nv_bfloat16& h, __nv_bfloat16& l) {
    h = __float2bfloat16_rn(a);
    l = __float2bfloat16_rn(a - __bfloat162float(h));
}

__device__ __forceinline__ void store4_split(__nv_bfloat16* Hrow, __nv_bfloat16* Lrow,
                                             int c, float4 v) {
    __nv_bfloat16 h0, l0, h1, l1, h2, l2, h3, l3;
    split_bf(v.x, h0, l0); split_bf(v.y, h1, l1);
    split_bf(v.z, h2, l2); split_bf(v.w, h3, l3);
    *(__nv_bfloat162*)(Hrow + c)     = __halves2bfloat162(h0, h1);
    *(__nv_bfloat162*)(Hrow + c + 2) = __halves2bfloat162(h2, h3);
    *(__nv_bfloat162*)(Lrow + c)     = __halves2bfloat162(l0, l1);
    *(__nv_bfloat162*)(Lrow + c + 2) = __halves2bfloat162(l2, l3);
}

#define LDMX4(r0, r1, r2, r3, addr) \
    asm volatile("ldmatrix.sync.aligned.m8n8.x4.shared.b16 {%0,%1,%2,%3},[%4];" \
                 : "=r"(r0), "=r"(r1), "=r"(r2), "=r"(r3) : "r"(addr))

#define LDMX2T(r0, r1, addr) \
    asm volatile("ldmatrix.sync.aligned.m8n8.x2.trans.shared.b16 {%0,%1},[%2];" \
                 : "=r"(r0), "=r"(r1) : "r"(addr))

#define MMA_BF16(d, a0, a1, a2, a3, b0, b1) \
    asm volatile("mma.sync.aligned.m16n8k16.row.col.f32.bf16.bf16.f32 " \
                 "{%0,%1,%2,%3},{%4,%5,%6,%7},{%8,%9},{%0,%1,%2,%3};" \
                 : "+f"(d[0]), "+f"(d[1]), "+f"(d[2]), "+f"(d[3]) \
                 : "r"(a0), "r"(a1), "r"(a2), "r"(a3), "r"(b0), "r"(b1))

#define REDV4(ptr, v0, v1, v2, v3) \
    asm volatile("red.global.add.v4.f32 [%0], {%1,%2,%3,%4];" \
                 :: "l"(ptr), "f"(v0), "f"(v1), "f"(v2), "f"(v3) : "memory")
#undef REDV4
#define REDV4(ptr, v0, v1, v2, v3) \
    asm volatile("red.global.add.v4.f32 [%0], {%1,%2,%3,%4};" \
                 :: "l"(ptr), "f"(v0), "f"(v1), "f"(v2), "f"(v3) : "memory")

// C[64x128] += A[64x128] * B[128x128], split-2 bf16 (3 MMAs/frag-pair).
// 8 warps: warp w -> rows (w&3)*16..+16, cols (w>>2)*64..+64. acc[8][4].
__device__ __forceinline__ void mma_tile(char* smem, int wid, int lane,
                                         float acc[8][4]) {
    int rw = (wid & 3) * 16;
    int ch = (wid >> 2) * 64;
    uint32_t aH = smem_u32((__nv_bfloat16*)smem
                           + (rw + (lane & 15)) * ASTRIDE + ((lane >> 4) * 8));
    uint32_t bH = smem_u32((__nv_bfloat16*)(smem + 2 * A_BYTES)
                           + (lane & 15) * ASTRIDE + ch);

    #pragma unroll
    for (int ks = 0; ks < 8; ks++) {
        uint32_t ao = aH + ks * 32;               // +16 bf16 along k
        uint32_t ah0, ah1, ah2, ah3, al0, al1, al2, al3;
        LDMX4(ah0, ah1, ah2, ah3, ao);
        LDMX4(al0, al1, al2, al3, ao + A_BYTES);
        uint32_t br = bH + ks * (16 * ASTRIDE * 2);   // +16 k-rows
        #pragma unroll
        for (int nt = 0; nt < 8; nt++) {
            uint32_t ba = br + nt * 16;
            uint32_t bh0, bh1, bl0, bl1;
            LDMX2T(bh0, bh1, ba);
            LDMX2T(bl0, bl1, ba + B_BYTES);
            MMA_BF16(acc[nt], al0, al1, al2, al3, bh0, bh1);
            MMA_BF16(acc[nt], ah0, ah1, ah2, ah3, bl0, bl1);
            MMA_BF16(acc[nt], ah0, ah1, ah2, ah3, bh0, bh1);
        }
    }
}

// Load pre-split weight matrix w (128x128 bf16 hi/lo) into smem B tiles.
__device__ __forceinline__ void load_B(char* smem, int widx, int tid) {
    __nv_bfloat16* Bh = (__nv_bfloat16*)(smem + 2 * A_BYTES);
    __nv_bfloat16* Bl = (__nv_bfloat16*)(smem + 2 * A_BYTES + B_BYTES);
    const uint4* srcH = (const uint4*)(g_Wh + (size_t)widx * D * D);
    const uint4* srcL = (const uint4*)(g_Wl + (size_t)widx * D * D);
    // 128x128 bf16 = 2048 uint4 per half
    for (int f = tid; f < 2048; f += 256) {
        int k = f >> 4, c8 = (f & 15) * 8;
        *(uint4*)(Bh + k * ASTRIDE + c8) = srcH[f];
        *(uint4*)(Bl + k * ASTRIDE + c8) = srcL[f];
    }
}

// ---------------------------------------------------------------------------
__global__ void k_split_w(const float* __restrict__ Wt, const float* __restrict__ We2,
                          const float* __restrict__ Wself, const float* __restrict__ W1) {
    int i = blockIdx.x * blockDim.x + threadIdx.x;   // 7*128*128/2 iters of 2
    int idx = i * 2;
    if (idx >= 7 * D * D) return;
    int m = idx / (D * D), r = idx % (D * D);
    const float* src = (m < 4) ? (Wt + (size_t)m * D * D + r)
                     : (m == 4 ? We2 + r : (m == 5 ? Wself + r : W1 + r));
    float2 v = *(const float2*)src;
    __nv_bfloat16 h0, l0, h1, l1;
    split_bf(v.x, h0, l0); split_bf(v.y, h1, l1);
    *(__nv_bfloat162*)(g_Wh + idx) = __halves2bfloat162(h0, h1);
    *(__nv_bfloat162*)(g_Wl + idx) = __halves2bfloat162(l0, l1);
}

// ---------------------------------------------------------------------------
__global__ void k_zero(int N) {
    size_t nA4 = (size_t)TTYPES * N * D / 4;
    size_t nS4 = (size_t)N * D / 4;
    size_t nC  = (size_t)TTYPES * N;
    size_t stride = (size_t)gridDim.x * blockDim.x;
    size_t i0 = (size_t)blockIdx.x * blockDim.x + threadIdx.x;
    float4 z = make_float4(0.f, 0.f, 0.f, 0.f);
    float4* A4 = (float4*)g_A;
    float4* S4 = (float4*)g_S;
    for (size_t i = i0; i < nA4; i += stride) A4[i] = z;
    for (size_t i = i0; i < nS4; i += stride) S4[i] = z;
    for (size_t i = i0; i < nC;  i += stride) g_cnt[i] = 0;
}

// ---------------------------------------------------------------------------
// One warp per edge: g_A[type][row] += x[col] (red.v4); counts.
__global__ void k_scatter(const float* __restrict__ x, const int* __restrict__ ei,
                          const int* __restrict__ et, int N, int E) {
    int w = (int)(((size_t)blockIdx.x * blockDim.x + threadIdx.x) >> 5);
    int lane = threadIdx.x & 31;
    if (w >= E) return;
    int row = __ldg(ei + w);        // destination
    int col = __ldg(ei + E + w);    // source (gathered)
    int t   = __ldg(et + w);
    float4 v = *(const float4*)(x + (size_t)col * D + lane * 4);
    float* p = g_A + ((size_t)t * N + row) * D + lane * 4;
    REDV4(p, v.x, v.y, v.z, v.w);
    if (lane == 0) atomicAdd(&g_cnt[t * N + row], 1);
}

// ---------------------------------------------------------------------------
// H = relu(ef @ W1 + b1) via split-bf16 MMA; scatter-add H into g_S[row].
// 64-edge tiles, 2 blocks/SM.
__global__ void __launch_bounds__(256, 2)
k_edge_mlp(const float* __restrict__ ef, const int* __restrict__ ei,
           const float* __restrict__ b1, int N, int E) {
    extern __shared__ char smem[];
    __nv_bfloat16* Ah = (__nv_bfloat16*)smem;
    __nv_bfloat16* Al = (__nv_bfloat16*)(smem + A_BYTES);
    int tid = threadIdx.x, wid = tid >> 5, lane = tid & 31;
    size_t e0 = (size_t)blockIdx.x * 64;

    // A = ef tile [64 edges][128 k] split into hi/lo
    for (int idx = tid; idx < 64 * 32; idx += 256) {
        int r = idx >> 5, c4 = (idx & 31) * 4;
        float4 v = make_float4(0.f, 0.f, 0.f, 0.f);
        size_t e = e0 + r;
        if (e < (size_t)E) v = *(const float4*)(ef + e * D + c4);
        store4_split(Ah + r * ASTRIDE, Al + r * ASTRIDE, c4, v);
    }
    load_B(smem, 6, tid);    // W1 pre-split
    __syncthreads();

    float acc[8][4] = {};
    mma_tile(smem, wid, lane, acc);

    // Round-trip through smem so the scatter is float4-contiguous per edge.
    __syncthreads();
    float* S = (float*)smem;   // [64][132]
    {
        int rw = (wid & 3) * 16, ch = (wid >> 2) * 64;
        int r0 = rw + (lane >> 2);
        int cp = (lane & 3) * 2;
        #pragma unroll
        for (int nt = 0; nt < 8; nt++) {
            int c = ch + nt * 8 + cp;
            S[r0 * 132 + c]           = acc[nt][0];
            S[r0 * 132 + c + 1]       = acc[nt][1];
            S[(r0 + 8) * 132 + c]     = acc[nt][2];
            S[(r0 + 8) * 132 + c + 1] = acc[nt][3];
        }
    }
    __syncthreads();

    float4 bb = __ldg((const float4*)b1 + lane);
    for (int it = 0; it < 8; it++) {
        int el = it * 8 + wid;
        size_t e = e0 + el;
        if (e < (size_t)E) {
            int dst = __ldg(ei + e);
            const float* Sr = S + el * 132 + lane * 4;
            float v0 = fmaxf(Sr[0] + bb.x, 0.f);
            float v1 = fmaxf(Sr[1] + bb.y, 0.f);
            float v2 = fmaxf(Sr[2] + bb.z, 0.f);
            float v3 = fmaxf(Sr[3] + bb.w, 0.f);
            float* p = g_S + (size_t)dst * D + lane * 4;
            REDV4(p, v0, v1, v2, v3);
        }
    }
}

// ---------------------------------------------------------------------------
// out[n] = sum over 6 K-segments (A_t@W_t, S@W_e2, x@W_self) + count-weighted
// biases, then LayerNorm + ReLU. 64-node tiles, 2 blocks/SM.
__global__ void __launch_bounds__(256, 2)
k_final(const float* __restrict__ x,
        const float* __restrict__ b_types, const float* __restrict__ b_self,
        const float* __restrict__ b_e2,
        const float* __restrict__ ln_g, const float* __restrict__ ln_b,
        float* __restrict__ out, int N) {
    extern __shared__ char smem[];
    __shared__ float Ps[1024];  // [0,512) b_types, 512 b_e2, 640 b_self, 768 ln_g, 896 ln_b
    __nv_bfloat16* Ah = (__nv_bfloat16*)smem;
    __nv_bfloat16* Al = (__nv_bfloat16*)(smem + A_BYTES);
    int tid = threadIdx.x, wid = tid >> 5, lane = tid & 31;
    int n0 = blockIdx.x * 64;

    for (int f = tid; f < 1024; f += 256) {
        float v;
        if (f < 512)      v = b_types[f];
        else if (f < 640) v = b_e2[f - 512];
        else if (f < 768) v = b_self[f - 640];
        else if (f < 896) v = ln_g[f - 768];
        else              v = ln_b[f - 896];
        Ps[f] = v;
    }

    float acc[8][4] = {};
    for (int seg = 0; seg < 6; seg++) {
        const float* Ab = (seg < 4) ? (g_A + (size_t)seg * N * D)
                                    : (seg == 4 ? g_S : x);
        __syncthreads();
        for (int idx = tid; idx < 64 * 32; idx += 256) {
            int r = idx >> 5, c4 = (idx & 31) * 4;
            float4 v = make_float4(0.f, 0.f, 0.f, 0.f);
            int n = n0 + r;
            if (n < N) v = *(const float4*)(Ab + (size_t)n * D + c4);
            store4_split(Ah + r * ASTRIDE, Al + r * ASTRIDE, c4, v);
        }
        load_B(smem, seg, tid);
        __syncthreads();
        mma_tile(smem, wid, lane, acc);
    }

    // Epilogue via smem round-trip (full rows needed for LayerNorm).
    __syncthreads();
    float* S = (float*)smem;   // [64][132]
    {
        int rw = (wid & 3) * 16, ch = (wid >> 2) * 64;
        int r0 = rw + (lane >> 2);
        int cp = (lane & 3) * 2;
        #pragma unroll
        for (int nt = 0; nt < 8; nt++) {
            int c = ch + nt * 8 + cp;
            S[r0 * 132 + c]           = acc[nt][0];
            S[r0 * 132 + c + 1]       = acc[nt][1];
            S[(r0 + 8) * 132 + c]     = acc[nt][2];
            S[(r0 + 8) * 132 + c + 1] = acc[nt][3];
        }
    }
    __syncthreads();

    // Each warp: 8 rows; 32 lanes cover 128 cols (4 each).
    for (int it = 0; it < 8; it++) {
        int r = wid * 8 + it;
        int n = n0 + r;
        bool valid = n < N;
        float c0 = 0.f, c1 = 0.f, c2 = 0.f, c3 = 0.f;
        if (valid) {
            c0 = (float)__ldg(&g_cnt[0 * N + n]);
            c1 = (float)__ldg(&g_cnt[1 * N + n]);
            c2 = (float)__ldg(&g_cnt[2 * N + n]);
            c3 = (float)__ldg(&g_cnt[3 * N + n]);
        }
        float ct = c0 + c1 + c2 + c3;
        float v[4];
        float s1 = 0.f, s2 = 0.f;
        #pragma unroll
        for (int j = 0; j < 4; j++) {
            int col = lane * 4 + j;
            float val = S[r * 132 + col]
                + c0 * Ps[0 * D + col] + c1 * Ps[1 * D + col]
                + c2 * Ps[2 * D + col] + c3 * Ps[3 * D + col]
                + ct * Ps[512 + col] + Ps[640 + col];
            v[j] = val;
            s1 += val;
            s2 += val * val;
        }
        #pragma unroll
        for (int m = 1; m < 32; m <<= 1) {
            s1 += __shfl_xor_sync(0xffffffff, s1, m);
            s2 += __shfl_xor_sync(0xffffffff, s2, m);
        }
        float mean = s1 * (1.f / D);
        float var  = s2 * (1.f / D) - mean * mean;
        float inv  = rsqrtf(var + 1e-5f);
        if (valid) {
            float4 o;
            #pragma unroll
            for (int j = 0; j < 4; j++) {
                int col = lane * 4 + j;
                float rres = (v[j] - mean) * inv * Ps[768 + col] + Ps[896 + col];
                (&o.x)[j] = rres > 0.f ? rres : 0.f;
            }
            *(float4*)(out + (size_t)n * D + lane * 4) = o;
        }
    }
}

// ---------------------------------------------------------------------------
extern "C" void kernel_launch(void* const* d_in, const int* in_sizes, int n_in,
                              void* d_out, int out_size) {
    const float* x   = (const float*)d_in[0];
    const int*   ei  = (const int*)d_in[1];
    const int*   et  = (const int*)d_in[2];
    const float* ef  = (const float*)d_in[3];
    const float* Wt  = (const float*)d_in[4];
    const float* bt  = (const float*)d_in[5];
    const float* Ws  = (const float*)d_in[6];
    const float* bs  = (const float*)d_in[7];
    const float* W1  = (const float*)d_in[8];
    const float* b1  = (const float*)d_in[9];
    const float* W2  = (const float*)d_in[10];
    const float* b2  = (const float*)d_in[11];
    const float* lg  = (const float*)d_in[12];
    const float* lb  = (const float*)d_in[13];
    float* out = (float*)d_out;

    int N = in_sizes[0] / D;
    int E = in_sizes[2];

    cudaFuncSetAttribute(k_edge_mlp, cudaFuncAttributeMaxDynamicSharedMemorySize, SMEM_BYTES);
    cudaFuncSetAttribute(k_final,    cudaFuncAttributeMaxDynamicSharedMemorySize, SMEM_BYTES);

    k_split_w<<<(7 * D * D / 2 + 255) / 256, 256>>>(Wt, W2, Ws, W1);
    k_zero<<<2048, 256>>>(N);
    k_scatter<<<(E + 7) / 8, 256>>>(x, ei, et, N, E);
    k_edge_mlp<<<(E + 63) / 64, 256, SMEM_BYTES>>>(ef, ei, b1, N, E);
    k_final<<<(N + 63) / 64, 256, SMEM_BYTES>>>(x, bt, bs, b2, lg, lb, out, N);
}